// round 17
// baseline (speedup 1.0000x reference)
#include <cuda_runtime.h>
#include <cuda_fp16.h>
#include <cstdint>
#include <math.h>

#define I_ 64
#define R_ 36
#define D_ 1024
#define C_ 64
#define W_ 32
#define N_ (I_*R_)       // 2304
#define MROWS (C_*W_)    // 2048
#define SMOOTH_ 9.0f
#define EPS_ 1e-8f
#define MASK_VAL_ (-1.0f)

// GEMM tiling (fp16 single-product, 3-stage pipeline)
#define BM 64
#define BN 128
#define BK 32
#define NSTAGE (D_/BK)           // 32
#define ROWB 80
#define TA (BM*ROWB)             // 5120
#define TB (BN*ROWB)             // 10240
#define STGB (TA + TB)           // 15360
#define NPIPE 3
#define GEMM_SMEM (NPIPE*STGB)   // 46080
#define MB2 (MROWS/BM)           // 32
#define NB2 (N_/BN)              // 18
#define GEMMB (NB2*MB2)          // 576

// Gram k-split
#define GCH 8
#define GSZ (I_*R_*R_)           // 82944
#define GRAMB (I_ * GCH)         // 512

// mega-kernel partition (4 chunks/thread)
#define ACH (MROWS * (D_/8))     // 262144
#define BCH (N_ * (D_/8))        // 294912
#define AB (ACH/1024)            // 256 blocks (8 rows each)
#define BB (BCH/1024)            // 288 blocks
#define MASKB 8
#define MEGAB (AB + BB + MASKB)

// post2 dynamic smem layout (floats)
#define P2_GS    0                        // [36][36]
#define P2_SS    (P2_GS + R_*R_)          // [8][32][37]
#define P2_RCN   (P2_SS + 8*32*37)        // [64][38]
#define P2_TOTAL (P2_RCN + 64*38)
#define POST2_SMEM (P2_TOTAL * 4)         // ~53KB

// ---- static scratch ----
__device__ float d_S[MROWS * N_];
__device__ float d_Gp[GCH][GSZ];
__device__ float d_capn[C_ * W_];
__device__ int   d_act_total;

__device__ __half d_Ah[MROWS * D_];
__device__ __half d_Bh[N_ * D_];

// ================= PTX helpers =================
__device__ __forceinline__ uint32_t smem_u32(const void* p) {
    uint32_t a;
    asm("{ .reg .u64 t; cvta.to.shared.u64 t, %1; cvt.u32.u64 %0, t; }" : "=r"(a) : "l"(p));
    return a;
}
__device__ __forceinline__ void cpasync16(uint32_t dst, const void* src) {
    asm volatile("cp.async.cg.shared.global [%0], [%1], 16;" :: "r"(dst), "l"(src) : "memory");
}
#define CP_COMMIT() asm volatile("cp.async.commit_group;" ::: "memory")
#define CP_WAIT(n)  asm volatile("cp.async.wait_group %0;" :: "n"(n) : "memory")

__device__ __forceinline__ void ldsm4(uint32_t r[4], uint32_t addr) {
    asm volatile("ldmatrix.sync.aligned.m8n8.x4.shared.b16 {%0,%1,%2,%3}, [%4];"
                 : "=r"(r[0]), "=r"(r[1]), "=r"(r[2]), "=r"(r[3]) : "r"(addr));
}
__device__ __forceinline__ void mma16816(float* d, const uint32_t* a, const uint32_t* b0, const uint32_t* b1) {
    asm volatile("mma.sync.aligned.m16n8k16.row.col.f32.f16.f16.f32 "
                 "{%0,%1,%2,%3},{%4,%5,%6,%7},{%8,%9},{%0,%1,%2,%3};"
                 : "+f"(d[0]), "+f"(d[1]), "+f"(d[2]), "+f"(d[3])
                 : "r"(a[0]), "r"(a[1]), "r"(a[2]), "r"(a[3]), "r"(*b0), "r"(*b1));
}

// block-local exclusive scan of cap_lens into offs[0..64] (parallel)
__device__ __forceinline__ void compute_offs(const int* __restrict__ cap_lens,
                                             int* cl, int* offs, int tid) {
    if (tid < C_) cl[tid] = cap_lens[tid];
    __syncthreads();
    if (tid <= C_) {
        int run = 0;
        for (int j = 0; j < tid; j++) run += cl[j];
        offs[tid] = run;
    }
    __syncthreads();
}
__device__ __forceinline__ int find_c(const int* offs, int row) {
    int lo = 0, hi = C_;
    #pragma unroll
    for (int it = 0; it < 6; it++) {
        int mid = (lo + hi) >> 1;
        if (offs[mid] <= row) lo = mid; else hi = mid;
    }
    return lo;
}

// ============================================================
// mega kernel: convert (4 chunks/thread, capn fused into A) + masks
// ============================================================
__global__ void __launch_bounds__(256) mega_kernel(const float* __restrict__ caps,
                                                   const float* __restrict__ imgs,
                                                   const int* __restrict__ cap_lens,
                                                   float* __restrict__ out) {
    __shared__ int cl[C_], offs[C_ + 1];
    __shared__ float rs[8][4];
    int b = blockIdx.x, tid = threadIdx.x;
    int wid = tid >> 5, lane = tid & 31;

    if (b < AB) {
        // ---- A convert: 8 full gathered rows, capn fused ----
        compute_offs(cap_lens, cl, offs, tid);
        int act = offs[C_];
        float4 va[4][2];
        #pragma unroll
        for (int k = 0; k < 4; k++) {
            int ci = b * 1024 + k * 256 + tid;
            int row = ci >> 7, c8 = ci & 127;
            int srcrow = 0;
            if (row < act) {
                int c = find_c(offs, row);
                srcrow = c * W_ + (row - offs[c]);
            }
            const float* src = caps + (size_t)srcrow * D_ + c8 * 8;
            va[k][0] = *reinterpret_cast<const float4*>(src);
            va[k][1] = *reinterpret_cast<const float4*>(src + 4);
        }
        float ps[4];
        #pragma unroll
        for (int k = 0; k < 4; k++) {
            int ci = b * 1024 + k * 256 + tid;
            int row = ci >> 7, c8 = ci & 127;
            float v[8] = {va[k][0].x, va[k][0].y, va[k][0].z, va[k][0].w,
                          va[k][1].x, va[k][1].y, va[k][1].z, va[k][1].w};
            union { __half h[8]; uint4 u; } Hi;
            float s = 0.f;
            #pragma unroll
            for (int j = 0; j < 8; j++) {
                Hi.h[j] = __float2half_rn(v[j]);
                s = fmaf(v[j], v[j], s);
            }
            *reinterpret_cast<uint4*>(d_Ah + (size_t)row * D_ + c8 * 8) = Hi.u;
            ps[k] = s;
        }
        // capn: reduce per row (warps 0-3 -> row 2k, 4-7 -> row 2k+1)
        #pragma unroll
        for (int k = 0; k < 4; k++) {
            float r = ps[k];
            #pragma unroll
            for (int o = 16; o; o >>= 1) r += __shfl_xor_sync(~0u, r, o);
            if (lane == 0) rs[2 * k + (wid >> 2)][wid & 3] = r;
        }
        __syncthreads();
        if (tid < 8) {
            float s = rs[tid][0] + rs[tid][1] + rs[tid][2] + rs[tid][3];
            int row = b * 8 + tid;
            if (row < act) {
                int c = find_c(offs, row);
                d_capn[c * W_ + (row - offs[c])] = s;
            }
        }
        return;
    }
    if (b < AB + BB) {
        // ---- B convert: 4 chunks/thread ----
        int bb = b - AB;
        float4 va[4][2];
        #pragma unroll
        for (int k = 0; k < 4; k++) {
            int ci = bb * 1024 + k * 256 + tid;
            int row = ci >> 7, c8 = ci & 127;
            const float* src = imgs + (size_t)row * D_ + c8 * 8;
            va[k][0] = *reinterpret_cast<const float4*>(src);
            va[k][1] = *reinterpret_cast<const float4*>(src + 4);
        }
        #pragma unroll
        for (int k = 0; k < 4; k++) {
            int ci = bb * 1024 + k * 256 + tid;
            int row = ci >> 7, c8 = ci & 127;
            float v[8] = {va[k][0].x, va[k][0].y, va[k][0].z, va[k][0].w,
                          va[k][1].x, va[k][1].y, va[k][1].z, va[k][1].w};
            union { __half h[8]; uint4 u; } Hi;
            #pragma unroll
            for (int j = 0; j < 8; j++) Hi.h[j] = __float2half_rn(v[j]);
            *reinterpret_cast<uint4*>(d_Bh + (size_t)row * D_ + c8 * 8) = Hi.u;
        }
        return;
    }
    // ---- masks + act_total (8 blocks x 8 c's) ----
    {
        int j = b - AB - BB;
        if (tid < C_) cl[tid] = cap_lens[tid];
        __syncthreads();
        if (j == 0 && tid == 0) {
            int run = 0;
            for (int q = 0; q < C_; q++) run += cl[q];
            d_act_total = run;
        }
        for (int idx = tid; idx < 8 * I_ * W_; idx += 256) {
            int c = j * 8 + (idx >> 11);
            int rem = idx & 2047;
            int i = rem >> 5, w = rem & 31;
            if (w >= cl[c])
                out[((size_t)i * C_ + c) * W_ + w] = MASK_VAL_;
        }
    }
}

// ============================================================
// HMMA fp16 GEMM (BM=64, 4 CTAs/SM, 3-stage) + gram tail blocks
// ============================================================
__global__ void __launch_bounds__(256, 4) gemm_mma_kernel(const float* __restrict__ imgs) {
    extern __shared__ __align__(128) char smc[];
    int tid = threadIdx.x;
    int b = blockIdx.x;

    if (b >= GEMMB) {
        // ---- gram block (reuses dynamic smem: 19008 < 46080) ----
        int gb = b - GEMMB;
        int i = gb >> 3, ch = gb & 7;
        float* sm = reinterpret_cast<float*>(smc);   // [36][132]
        const float* base = imgs + (size_t)i * R_ * D_ + ch * 128;
        for (int idx = tid; idx < R_ * 32; idx += 256) {
            int r = idx >> 5, d4 = idx & 31;
            float4 v = *reinterpret_cast<const float4*>(base + r * D_ + d4 * 4);
            *reinterpret_cast<float4*>(&sm[r * 132 + d4 * 4]) = v;
        }
        __syncthreads();
        if (tid < 144) {
            int tr = tid / 12, tc = tid % 12;
            float acc[3][3] = {};
            #pragma unroll 2
            for (int d = 0; d < 128; d += 4) {
                float4 A0 = *reinterpret_cast<const float4*>(&sm[(tr*3+0)*132 + d]);
                float4 A1 = *reinterpret_cast<const float4*>(&sm[(tr*3+1)*132 + d]);
                float4 A2 = *reinterpret_cast<const float4*>(&sm[(tr*3+2)*132 + d]);
                float4 B0 = *reinterpret_cast<const float4*>(&sm[(tc*3+0)*132 + d]);
                float4 B1 = *reinterpret_cast<const float4*>(&sm[(tc*3+1)*132 + d]);
                float4 B2 = *reinterpret_cast<const float4*>(&sm[(tc*3+2)*132 + d]);
                acc[0][0] = fmaf(A0.x,B0.x,fmaf(A0.y,B0.y,fmaf(A0.z,B0.z,fmaf(A0.w,B0.w,acc[0][0]))));
                acc[0][1] = fmaf(A0.x,B1.x,fmaf(A0.y,B1.y,fmaf(A0.z,B1.z,fmaf(A0.w,B1.w,acc[0][1]))));
                acc[0][2] = fmaf(A0.x,B2.x,fmaf(A0.y,B2.y,fmaf(A0.z,B2.z,fmaf(A0.w,B2.w,acc[0][2]))));
                acc[1][0] = fmaf(A1.x,B0.x,fmaf(A1.y,B0.y,fmaf(A1.z,B0.z,fmaf(A1.w,B0.w,acc[1][0]))));
                acc[1][1] = fmaf(A1.x,B1.x,fmaf(A1.y,B1.y,fmaf(A1.z,B1.z,fmaf(A1.w,B1.w,acc[1][1]))));
                acc[1][2] = fmaf(A1.x,B2.x,fmaf(A1.y,B2.y,fmaf(A1.z,B2.z,fmaf(A1.w,B2.w,acc[1][2]))));
                acc[2][0] = fmaf(A2.x,B0.x,fmaf(A2.y,B0.y,fmaf(A2.z,B0.z,fmaf(A2.w,B0.w,acc[2][0]))));
                acc[2][1] = fmaf(A2.x,B1.x,fmaf(A2.y,B1.y,fmaf(A2.z,B1.z,fmaf(A2.w,B1.w,acc[2][1]))));
                acc[2][2] = fmaf(A2.x,B2.x,fmaf(A2.y,B2.y,fmaf(A2.z,B2.z,fmaf(A2.w,B2.w,acc[2][2]))));
            }
            float* dst = d_Gp[ch] + i * (R_*R_);
            #pragma unroll
            for (int a = 0; a < 3; a++)
                #pragma unroll
                for (int bb = 0; bb < 3; bb++)
                    dst[(tr*3+a) * R_ + (tc*3+bb)] = acc[a][bb];
        }
        return;
    }

    uint32_t sb = smem_u32(smc);
    int wid = tid >> 5, lane = tid & 31;

    int act = d_act_total;
    int mblk = b / NB2, nblk = b % NB2;
    if (mblk * BM >= act) return;

    int wr = wid & 1, wc = wid >> 1;

    const __half* srcA = d_Ah + (size_t)mblk * BM * D_;
    const __half* srcB = d_Bh + (size_t)nblk * BN * D_;

    int q = lane >> 3, lr = lane & 7;
    int rowoff = ((q & 1) << 3) + lr;
    int csel = q >> 1;
    uint32_t aoff = (uint32_t)((wr * 32 + rowoff) * ROWB + csel * 16);
    uint32_t boff = (uint32_t)((wc * 32 + rowoff) * ROWB + csel * 16);

    float acc[2][4][4] = {};

    #define LOAD_STAGE(s, k0) do {                                              \
        _Pragma("unroll")                                                        \
        for (int it = 0; it < 3; it++) {                                         \
            int ci = tid + it * 256;                                             \
            const char* g; uint32_t dd;                                          \
            if (ci < 256) {                                                      \
                int row = ci >> 2, cc = ci & 3;                                   \
                g = (const char*)(srcA + (size_t)row * D_ + (k0)) + cc * 16;      \
                dd = sb + (uint32_t)((s) * STGB + row * ROWB + cc * 16);          \
            } else {                                                              \
                int u = ci - 256;                                                 \
                int row = u >> 2, cc = u & 3;                                     \
                g = (const char*)(srcB + (size_t)row * D_ + (k0)) + cc * 16;      \
                dd = sb + (uint32_t)((s) * STGB + TA + row * ROWB + cc * 16);     \
            }                                                                     \
            cpasync16(dd, g);                                                     \
        }                                                                         \
        CP_COMMIT();                                                              \
    } while (0)

    LOAD_STAGE(0, 0);
    LOAD_STAGE(1, BK);

    int s = 0;
    for (int ks = 0; ks < NSTAGE; ks++) {
        if (ks + 2 < NSTAGE) {
            int lb = s + 2; if (lb >= NPIPE) lb -= NPIPE;
            LOAD_STAGE(lb, (ks + 2) * BK);
            CP_WAIT(2);
        } else if (ks + 2 == NSTAGE) {
            CP_WAIT(1);
        } else {
            CP_WAIT(0);
        }
        __syncthreads();

        uint32_t bAh = sb + (uint32_t)(s * STGB);
        uint32_t bBh = bAh + TA;

        #pragma unroll
        for (int k16 = 0; k16 < 2; k16++) {
            uint32_t kb = (uint32_t)(k16 * 32);
            uint32_t ah[2][4];
            uint32_t bhf[4][2];
            #pragma unroll
            for (int mt = 0; mt < 2; mt++)
                ldsm4(ah[mt], bAh + (uint32_t)(mt * 16 * ROWB) + kb + aoff);
            #pragma unroll
            for (int np = 0; np < 2; np++) {
                uint32_t t4[4];
                ldsm4(t4, bBh + (uint32_t)(np * 16 * ROWB) + kb + boff);
                bhf[np*2+0][0] = t4[0]; bhf[np*2+0][1] = t4[2];
                bhf[np*2+1][0] = t4[1]; bhf[np*2+1][1] = t4[3];
            }
            #pragma unroll
            for (int mt = 0; mt < 2; mt++)
                #pragma unroll
                for (int nt = 0; nt < 4; nt++)
                    mma16816(acc[mt][nt], ah[mt], &bhf[nt][0], &bhf[nt][1]);
        }
        __syncthreads();
        s = (s + 1 == NPIPE) ? 0 : s + 1;
    }

    int g = lane >> 2, tq = lane & 3;
    #pragma unroll
    for (int mt = 0; mt < 2; mt++) {
        int m0 = mblk * BM + wr * 32 + mt * 16 + g;
        #pragma unroll
        for (int nt = 0; nt < 4; nt++) {
            int n = nblk * BN + wc * 32 + nt * 8 + tq * 2;
            if (m0 < act)
                *reinterpret_cast<float2*>(d_S + (size_t)m0 * N_ + n) =
                    make_float2(acc[mt][nt][0], acc[mt][nt][1]);
            if (m0 + 8 < act)
                *reinterpret_cast<float2*>(d_S + (size_t)(m0 + 8) * N_ + n) =
                    make_float2(acc[mt][nt][2], acc[mt][nt][3]);
        }
    }
}

// ============================================================
// post2: fused G-reduce + norms + softmax + symmetric quad form.
// ============================================================
__global__ void __launch_bounds__(256, 3) post2_kernel(const int* __restrict__ cap_lens,
                                                       float* __restrict__ out) {
    extern __shared__ float dyn[];
    float* Gs  = dyn + P2_GS;            // [36][36]
    float* Ss  = dyn + P2_SS;            // [8][32][37] flat
    float* rcn = dyn + P2_RCN;           // [64][38]
    __shared__ int cl[C_], offs[C_ + 1];

    int i = blockIdx.x;
    int tid = threadIdx.x, wid = tid >> 5, lane = tid & 31;

    compute_offs(cap_lens, cl, offs, tid);
    int act = offs[C_];
    int base0 = blockIdx.y * 256;
    if (base0 >= act) return;

    // reduce gram partials while loading G
    for (int idx = tid; idx < R_ * R_; idx += 256) {
        float s = 0.f;
        #pragma unroll
        for (int p = 0; p < GCH; p++) s += d_Gp[p][i * (R_*R_) + idx];
        Gs[idx] = s;
    }

    int blk_rows = act - base0;
    if (blk_rows > 256) blk_rows = 256;

    // stage S rows (warp per 32 rows)
    {
        int m0w = base0 + wid * 32;
        int nrows = act - m0w;
        if (nrows > 32) nrows = 32;
        if (nrows < 0) nrows = 0;
        for (int idx = lane; idx < nrows * R_; idx += 32) {
            int row = idx / R_, r = idx - row * R_;
            Ss[(wid * 32 + row) * 37 + r] = d_S[(size_t)(m0w + row) * N_ + i * R_ + r];
        }
    }
    __syncthreads();

    // fused norms
    int c_lo = find_c(offs, base0);
    int c_hi = find_c(offs, base0 + blk_rows - 1);
    int ncs = c_hi - c_lo + 1;           // <= 64
    for (int item = tid; item < ncs * R_; item += 256) {
        int ci = item / R_, r = item - ci * R_;
        int c = c_lo + ci;
        int o = offs[c], nw2 = offs[c + 1] - o;
        float s = 0.f;
        for (int w = 0; w < nw2; w++) {
            int row = o + w;
            int lr2 = row - base0;
            float v = (lr2 >= 0 && lr2 < 256) ? Ss[lr2 * 37 + r]
                                              : d_S[(size_t)row * N_ + i * R_ + r];
            v = (v >= 0.f) ? v : 0.1f * v;
            s = fmaf(v, v, s);
        }
        rcn[ci * 38 + r] = SMOOTH_ / (sqrtf(s) + EPS_);
    }
    __syncthreads();

    int myrow = base0 + wid * 32 + lane;
    if (myrow < act && (wid * 32 + lane) < blk_rows) {
        int c = find_c(offs, myrow);
        int w = myrow - offs[c];
        const float* rc = rcn + (c - c_lo) * 38;
        const float* sr = Ss + (wid * 32 + lane) * 37;

        float a[R_];
        float sum0 = 0.f, sum1 = 0.f, sum2 = 0.f, sum3 = 0.f;
        float sd0 = 0.f, sd1 = 0.f, sd2 = 0.f, sd3 = 0.f;
        #pragma unroll
        for (int r = 0; r < R_; r += 4) {
            float v0 = sr[r+0], v1 = sr[r+1];
            float v2 = sr[r+2], v3 = sr[r+3];
            float l0 = (v0 >= 0.f) ? v0 : 0.1f * v0;
            float l1 = (v1 >= 0.f) ? v1 : 0.1f * v1;
            float l2 = (v2 >= 0.f) ? v2 : 0.1f * v2;
            float l3 = (v3 >= 0.f) ? v3 : 0.1f * v3;
            float e0 = __expf(l0 * rc[r+0]);
            float e1 = __expf(l1 * rc[r+1]);
            float e2 = __expf(l2 * rc[r+2]);
            float e3 = __expf(l3 * rc[r+3]);
            a[r+0] = e0; a[r+1] = e1; a[r+2] = e2; a[r+3] = e3;
            sum0 += e0; sum1 += e1; sum2 += e2; sum3 += e3;
            sd0 = fmaf(e0, v0, sd0); sd1 = fmaf(e1, v1, sd1);
            sd2 = fmaf(e2, v2, sd2); sd3 = fmaf(e3, v3, sd3);
        }
        float sum = (sum0 + sum1) + (sum2 + sum3);
        float sd  = (sd0 + sd1) + (sd2 + sd3);
        float inv = 1.f / sum;

        float qd = 0.f, qo0 = 0.f, qo1 = 0.f;
        #pragma unroll
        for (int rg = 0; rg < 9; rg++) {
            #pragma unroll
            for (int aa = 0; aa < 4; aa++) {
                float4 g4 = *reinterpret_cast<const float4*>(&Gs[(4*rg+aa) * R_ + 4*rg]);
                float t = g4.x * a[4*rg+0];
                t = fmaf(g4.y, a[4*rg+1], t);
                t = fmaf(g4.z, a[4*rg+2], t);
                t = fmaf(g4.w, a[4*rg+3], t);
                qd = fmaf(a[4*rg+aa], t, qd);
            }
            #pragma unroll
            for (int cg = rg + 1; cg < 9; cg++) {
                #pragma unroll
                for (int aa = 0; aa < 4; aa++) {
                    float4 g4 = *reinterpret_cast<const float4*>(&Gs[(4*rg+aa) * R_ + 4*cg]);
                    float t = g4.x * a[4*cg+0];
                    t = fmaf(g4.y, a[4*cg+1], t);
                    t = fmaf(g4.z, a[4*cg+2], t);
                    t = fmaf(g4.w, a[4*cg+3], t);
                    if ((cg ^ rg) & 1) qo0 = fmaf(a[4*rg+aa], t, qo0);
                    else               qo1 = fmaf(a[4*rg+aa], t, qo1);
                }
            }
        }
        float qe = qd + 2.f * (qo0 + qo1);

        float n = sqrtf(qe) * inv;
        float dot = sd * inv;
        float denom = n + EPS_;
        float w12 = dot / denom;
        float w2v = n / denom;
        float w1v = sqrtf(d_capn[c * W_ + w]);
        float sim = w12 / fmaxf(w1v * w2v, EPS_);
        out[((size_t)i * C_ + c) * W_ + w] = sim;
    }
}

// ============================================================
extern "C" void kernel_launch(void* const* d_in, const int* in_sizes, int n_in,
                              void* d_out, int out_size) {
    const float* imgs     = (const float*)d_in[0];
    const float* caps     = (const float*)d_in[1];
    const int*   cap_lens = (const int*)d_in[3];
    float* out = (float*)d_out;

    cudaFuncSetAttribute(gemm_mma_kernel, cudaFuncAttributeMaxDynamicSharedMemorySize, GEMM_SMEM);
    cudaFuncSetAttribute(post2_kernel, cudaFuncAttributeMaxDynamicSharedMemorySize, POST2_SMEM);

    mega_kernel<<<MEGAB, 256>>>(caps, imgs, cap_lens, out);
    gemm_mma_kernel<<<GEMMB + GRAMB, 256, GEMM_SMEM>>>(imgs);
    dim3 pgrid(I_, 8);
    post2_kernel<<<pgrid, 256, POST2_SMEM>>>(cap_lens, out);
}